// round 1
// baseline (speedup 1.0000x reference)
#include <cuda_runtime.h>
#include <cstddef>
#include <cstdint>

// Problem dims
#define BB 32
#define SB 2048
#define DD 256
#define HH 512
#define G4 2048   // 4*H
#define OO 256
#define BH (BB * HH)   // 16384 floats per timestep of h

// ---------------------------------------------------------------------------
// Scratch (device globals: allocation-free per harness rules)
// ---------------------------------------------------------------------------
__device__ float g_xg[(size_t)BB * SB * G4];   // [b][s][4H] input projections (512 MB)
__device__ float g_h [(size_t)SB * BH];        // [t][b][H] hidden states (128 MB)
__device__ unsigned g_bar_cnt;                 // grid barrier state (replay-safe)
__device__ unsigned g_bar_gen;

// ---------------------------------------------------------------------------
// f32x2 packed-FMA helpers (ptxas never emits FFMA2 from C++; PTX-only path)
// ---------------------------------------------------------------------------
__device__ __forceinline__ void ffma2(unsigned long long& acc, unsigned long long a,
                                      unsigned long long b) {
    asm("fma.rn.f32x2 %0, %1, %2, %0;" : "+l"(acc) : "l"(a), "l"(b));
}
__device__ __forceinline__ unsigned long long dup2(float x) {
    unsigned long long r;
    asm("mov.b64 %0, {%1, %1};" : "=l"(r) : "f"(x));
    return r;
}
__device__ __forceinline__ unsigned long long pack2(float lo, float hi) {
    unsigned long long r;
    asm("mov.b64 %0, {%1, %2};" : "=l"(r) : "f"(lo), "f"(hi));
    return r;
}
__device__ __forceinline__ void unpack2(unsigned long long v, float& lo, float& hi) {
    asm("mov.b64 {%0, %1}, %2;" : "=f"(lo), "=f"(hi) : "l"(v));
}
__device__ __forceinline__ float sigm(float x) { return 1.f / (1.f + __expf(-x)); }

// ---------------------------------------------------------------------------
// SGEMM: C[M,N] = A[M,K] @ B[K,N] + bias[N]   (all row-major, fp32)
// Block tile 64x64, BK=16, 128 threads, 8x4 register tile, f32x2 inner loop.
// REMAP: physical row p = t*32+m  ->  output row m*SB + t  (epilogue only)
// ---------------------------------------------------------------------------
template <bool REMAP>
__global__ __launch_bounds__(128)
void sgemm_f32x2(const float* __restrict__ A, const float* __restrict__ Bm,
                 const float* __restrict__ bias, float* __restrict__ C,
                 int M, int N, int K) {
    __shared__ float As[64 * 16];   // [m][k]
    __shared__ float Bs[16 * 64];   // [k][n]

    const int tid = threadIdx.x;
    const int tx  = tid & 15;       // n-group: 4 cols each
    const int ty  = tid >> 4;       // m-group: 8 rows each
    const int bn  = blockIdx.x * 64;
    const int bm  = blockIdx.y * 64;

    unsigned long long acc[8][2];
#pragma unroll
    for (int i = 0; i < 8; i++) { acc[i][0] = 0ull; acc[i][1] = 0ull; }

    const int ar = tid >> 2, ac = (tid & 3) * 4;   // A-tile loader coords
    const int br = tid >> 4, bc = (tid & 15) * 4;  // B-tile loader coords

    for (int k0 = 0; k0 < K; k0 += 16) {
#pragma unroll
        for (int p = 0; p < 2; p++) {
            int row = ar + p * 32;
            *(float4*)(As + row * 16 + ac) =
                *(const float4*)(A + (size_t)(bm + row) * K + k0 + ac);
        }
#pragma unroll
        for (int p = 0; p < 2; p++) {
            int row = br + p * 8;
            *(float4*)(Bs + row * 64 + bc) =
                *(const float4*)(Bm + (size_t)(k0 + row) * N + bn + bc);
        }
        __syncthreads();

#pragma unroll
        for (int kk = 0; kk < 16; kk++) {
            ulonglong2 w = *(const ulonglong2*)(Bs + kk * 64 + tx * 4);
#pragma unroll
            for (int im = 0; im < 8; im++) {
                unsigned long long ad = dup2(As[(ty * 8 + im) * 16 + kk]);
                ffma2(acc[im][0], ad, w.x);
                ffma2(acc[im][1], ad, w.y);
            }
        }
        __syncthreads();
    }

    float4 bvec = *(const float4*)(bias + bn + tx * 4);
#pragma unroll
    for (int im = 0; im < 8; im++) {
        int row = bm + ty * 8 + im;
        float x0, x1, x2, x3;
        unpack2(acc[im][0], x0, x1);
        unpack2(acc[im][1], x2, x3);
        float4 o = make_float4(x0 + bvec.x, x1 + bvec.y, x2 + bvec.z, x3 + bvec.w);
        size_t orow = REMAP ? ((size_t)(row & 31) * SB + (size_t)(row >> 5))
                            : (size_t)row;
        *(float4*)(C + orow * N + bn + tx * 4) = o;
    }
}

// ---------------------------------------------------------------------------
// Persistent LSTM recurrence kernel.
// Grid: 128 CTAs (<=148 SMs -> all co-resident; software grid barrier is safe).
// Each CTA owns 4 hidden units j0..j0+3 (16 gate columns). Wh slice (512x16,
// 32 KB) stays in SMEM for all 2048 steps. Per step: stage h[t-1] (32x512,
// padded stride 516 for bank-conflict-free access) into SMEM, each thread owns
// one (m, j) pair, computes its 4 gates with f32x2 FMAs, updates c (register-
// resident) and writes h[t][m][j]. Sense-reversing grid barrier between steps.
// hs row stride 516: bank = (4*m + k) % 32 -> 8 distinct banks per warp access.
// ---------------------------------------------------------------------------
#define HS_STRIDE 516

__global__ __launch_bounds__(128, 1)
void lstm_rec(const float* __restrict__ Wh) {
    extern __shared__ float sm[];
    float* Whs = sm;              // [512][16], layout [k][u*4+q]
    float* hs  = sm + HH * 16;    // [32][HS_STRIDE]

    const int tid = threadIdx.x;
    const int tm  = tid >> 2;     // batch row m, 0..31
    const int tn  = tid & 3;      // local unit, 0..3
    const int j0  = blockIdx.x * 4;
    const int j   = j0 + tn;
    const unsigned nb = gridDim.x;

    // Load Wh slice, interleaved so thread tn reads 4 contiguous gate cols:
    // Whs[k*16 + u*4 + q] = Wh[k][q*HH + j0 + u]
    for (int idx = tid; idx < HH * 16; idx += 128) {
        int k = idx >> 4, c = idx & 15, u = c >> 2, q = c & 3;
        Whs[idx] = Wh[(size_t)k * G4 + q * HH + j0 + u];
    }

    float cst = 0.f;
    const float* hrow = hs + tm * HS_STRIDE;

    for (int t = 0; t < SB; t++) {
        __syncthreads();   // prior-step hs readers are done before overwrite
        if (t == 0) {
            float4 z = make_float4(0.f, 0.f, 0.f, 0.f);
            for (int i = tid; i < BH / 4; i += 128) {
                int m = i >> 7, c = i & 127;
                *(float4*)(hs + m * HS_STRIDE + (c << 2)) = z;
            }
        } else {
            const float4* src = (const float4*)(g_h + (size_t)(t - 1) * BH);
            for (int i = tid; i < BH / 4; i += 128) {
                int m = i >> 7, c = i & 127;
                *(float4*)(hs + m * HS_STRIDE + (c << 2)) = __ldcg(src + m * 128 + c);
            }
        }
        __syncthreads();

        // Gate accumulators seeded with precomputed xg (bias already folded in)
        const float* xgp = g_xg + ((size_t)tm * SB + t) * G4;
        unsigned long long a01 = pack2(__ldcg(xgp + j),          __ldcg(xgp + HH + j));
        unsigned long long a23 = pack2(__ldcg(xgp + 2 * HH + j), __ldcg(xgp + 3 * HH + j));

#pragma unroll 4
        for (int k = 0; k < HH; k += 4) {
            float4 hv = *(const float4*)(hrow + k);
            const float* wb = Whs + k * 16 + tn * 4;
            {
                ulonglong2 w = *(const ulonglong2*)(wb);
                unsigned long long hd = dup2(hv.x);
                ffma2(a01, hd, w.x); ffma2(a23, hd, w.y);
            }
            {
                ulonglong2 w = *(const ulonglong2*)(wb + 16);
                unsigned long long hd = dup2(hv.y);
                ffma2(a01, hd, w.x); ffma2(a23, hd, w.y);
            }
            {
                ulonglong2 w = *(const ulonglong2*)(wb + 32);
                unsigned long long hd = dup2(hv.z);
                ffma2(a01, hd, w.x); ffma2(a23, hd, w.y);
            }
            {
                ulonglong2 w = *(const ulonglong2*)(wb + 48);
                unsigned long long hd = dup2(hv.w);
                ffma2(a01, hd, w.x); ffma2(a23, hd, w.y);
            }
        }

        float gi, gf, gg, go;
        unpack2(a01, gi, gf);
        unpack2(a23, gg, go);
        float si = sigm(gi), sf = sigm(gf), so = sigm(go);
        cst = sf * cst + si * tanhf(gg);
        float hn = so * tanhf(cst);
        __stcg(g_h + (size_t)t * BH + (size_t)tm * HH + j, hn);

        // ---- grid barrier (sense-reversing, replay-safe) ----
        __threadfence();
        __syncthreads();
        if (tid == 0) {
            unsigned g = *((volatile unsigned*)&g_bar_gen);
            unsigned old = atomicAdd(&g_bar_cnt, 1u);
            if (old == nb - 1u) {
                atomicExch(&g_bar_cnt, 0u);
                __threadfence();
                atomicAdd(&g_bar_gen, 1u);
            } else {
                while (*((volatile unsigned*)&g_bar_gen) == g) { __nanosleep(32); }
            }
        }
        __syncthreads();
    }
}

// ---------------------------------------------------------------------------
// Launch
// ---------------------------------------------------------------------------
extern "C" void kernel_launch(void* const* d_in, const int* in_sizes, int n_in,
                              void* d_out, int out_size) {
    // Identify inputs by element count (all sizes are distinct)
    const float *x = nullptr, *Wx = nullptr, *Wh = nullptr,
                *b = nullptr, *Wo = nullptr, *bo = nullptr;
    for (int i = 0; i < n_in; i++) {
        switch (in_sizes[i]) {
            case BB * SB * DD: x  = (const float*)d_in[i]; break;  // 16777216
            case DD * G4:      Wx = (const float*)d_in[i]; break;  // 524288
            case HH * G4:      Wh = (const float*)d_in[i]; break;  // 1048576
            case G4:           b  = (const float*)d_in[i]; break;  // 2048
            case HH * OO:      Wo = (const float*)d_in[i]; break;  // 131072
            case OO:           bo = (const float*)d_in[i]; break;  // 256
        }
    }

    float* xg;   cudaGetSymbolAddress((void**)&xg, g_xg);
    float* hall; cudaGetSymbolAddress((void**)&hall, g_h);

    // 1) xg = x @ Wx + b   (bias folded here; recurrence adds none)
    {
        dim3 grid(G4 / 64, (BB * SB) / 64);
        sgemm_f32x2<false><<<grid, 128>>>(x, Wx, b, xg, BB * SB, G4, DD);
    }

    // 2) persistent recurrence
    {
        int smem_bytes = (HH * 16 + 32 * HS_STRIDE) * (int)sizeof(float); // 98816
        cudaFuncSetAttribute(lstm_rec, cudaFuncAttributeMaxDynamicSharedMemorySize,
                             smem_bytes);
        lstm_rec<<<HH / 4, 128, smem_bytes>>>(Wh);
    }

    // 3) y = h @ Wo + bo, with [t][b] -> [b][t] row remap in the epilogue
    {
        dim3 grid(OO / 64, (BB * SB) / 64);
        sgemm_f32x2<true><<<grid, 128>>>(hall, Wo, bo, (float*)d_out,
                                         BB * SB, OO, HH);
    }
}

// round 4
// speedup vs baseline: 1.2108x; 1.2108x over previous
#include <cuda_runtime.h>
#include <cstddef>
#include <cstdint>

// Problem dims
#define BB 32
#define SB 2048
#define DD 256
#define HH 512
#define G4 2048   // 4*H
#define OO 256
#define BH (BB * HH)   // 16384 floats per timestep of h

// ---------------------------------------------------------------------------
// Scratch (device globals: allocation-free per harness rules)
// ---------------------------------------------------------------------------
__device__ float g_xg[(size_t)BB * SB * G4];   // [b][s][4H] input projections
__device__ float g_h [(size_t)SB * BH];        // [t][b][H] hidden states
__device__ unsigned g_bar_cnt;                 // grid barrier state (replay-safe)
__device__ unsigned g_bar_gen;

// ---------------------------------------------------------------------------
// f32x2 packed-FMA helpers
// ---------------------------------------------------------------------------
__device__ __forceinline__ void ffma2(unsigned long long& acc, unsigned long long a,
                                      unsigned long long b) {
    asm("fma.rn.f32x2 %0, %1, %2, %0;" : "+l"(acc) : "l"(a), "l"(b));
}
__device__ __forceinline__ unsigned long long dup2(float x) {
    unsigned long long r;
    asm("mov.b64 %0, {%1, %1};" : "=l"(r) : "f"(x));
    return r;
}
__device__ __forceinline__ unsigned long long pack2(float lo, float hi) {
    unsigned long long r;
    asm("mov.b64 %0, {%1, %2};" : "=l"(r) : "f"(lo), "f"(hi));
    return r;
}
__device__ __forceinline__ void unpack2(unsigned long long v, float& lo, float& hi) {
    asm("mov.b64 {%0, %1}, %2;" : "=f"(lo), "=f"(hi) : "l"(v));
}
__device__ __forceinline__ float sigm(float x) { return 1.f / (1.f + __expf(-x)); }

// ---------------------------------------------------------------------------
// SGEMM: C[M,N] = A[M,K] @ B[K,N] + bias[N] (row-major fp32), 64x64 tile,
// BK=16, 128 threads, 8x4 register tile, f32x2 inner loop. (unchanged, passing)
// ---------------------------------------------------------------------------
template <bool REMAP>
__global__ __launch_bounds__(128)
void sgemm_f32x2(const float* __restrict__ A, const float* __restrict__ Bm,
                 const float* __restrict__ bias, float* __restrict__ C,
                 int M, int N, int K) {
    __shared__ float As[64 * 16];
    __shared__ float Bs[16 * 64];

    const int tid = threadIdx.x;
    const int tx  = tid & 15;
    const int ty  = tid >> 4;
    const int bn  = blockIdx.x * 64;
    const int bm  = blockIdx.y * 64;

    unsigned long long acc[8][2];
#pragma unroll
    for (int i = 0; i < 8; i++) { acc[i][0] = 0ull; acc[i][1] = 0ull; }

    const int ar = tid >> 2, ac = (tid & 3) * 4;
    const int br = tid >> 4, bc = (tid & 15) * 4;

    for (int k0 = 0; k0 < K; k0 += 16) {
#pragma unroll
        for (int p = 0; p < 2; p++) {
            int row = ar + p * 32;
            *(float4*)(As + row * 16 + ac) =
                *(const float4*)(A + (size_t)(bm + row) * K + k0 + ac);
        }
#pragma unroll
        for (int p = 0; p < 2; p++) {
            int row = br + p * 8;
            *(float4*)(Bs + row * 64 + bc) =
                *(const float4*)(Bm + (size_t)(k0 + row) * N + bn + bc);
        }
        __syncthreads();

#pragma unroll
        for (int kk = 0; kk < 16; kk++) {
            ulonglong2 w = *(const ulonglong2*)(Bs + kk * 64 + tx * 4);
#pragma unroll
            for (int im = 0; im < 8; im++) {
                unsigned long long ad = dup2(As[(ty * 8 + im) * 16 + kk]);
                ffma2(acc[im][0], ad, w.x);
                ffma2(acc[im][1], ad, w.y);
            }
        }
        __syncthreads();
    }

    float4 bvec = *(const float4*)(bias + bn + tx * 4);
#pragma unroll
    for (int im = 0; im < 8; im++) {
        int row = bm + ty * 8 + im;
        float x0, x1, x2, x3;
        unpack2(acc[im][0], x0, x1);
        unpack2(acc[im][1], x2, x3);
        float4 o = make_float4(x0 + bvec.x, x1 + bvec.y, x2 + bvec.z, x3 + bvec.w);
        size_t orow = REMAP ? ((size_t)(row & 31) * SB + (size_t)(row >> 5))
                            : (size_t)row;
        *(float4*)(C + orow * N + bn + tx * 4) = o;
    }
}

// ---------------------------------------------------------------------------
// Persistent LSTM recurrence, v2b (v2 + proven nanosleep barrier).
// 128 CTAs x 256 threads (2 warps/SMSP). CTA owns 4 hidden units (16 gate
// cols); Wh slice (512x16 = 32KB) in SMEM for all 2048 steps. Split-K x2:
// thread (kh, m, tn) computes the 4 gate partial dots of unit j over k-half
// kh. Software-pipelined inner loop (register prefetch of next group's h + 4
// weight vectors), two accumulator sets to break FMA chains. kh=1 partials
// reduced to kh=0 via SMEM; kh=0 does the cell update. xg for step t+1 is
// prefetched during step t. Sense-reversing global barrier between steps
// (nanosleep backoff — identical to the R1 barrier that passed).
// ---------------------------------------------------------------------------
#define HS_STRIDE 516
#define KHALF 256

__global__ __launch_bounds__(256, 1)
void lstm_rec(const float* __restrict__ Wh) {
    extern __shared__ float sm[];
    float* Whs = sm;                         // [512][16]  (8192 floats)
    float* hs  = sm + HH * 16;               // [32][516]  (16512 floats)
    float* red = hs + 32 * HS_STRIDE;        // [128][4]   (512 floats)

    const int tid = threadIdx.x;
    const int kh  = tid >> 7;                // k-half 0/1
    const int r   = tid & 127;
    const int tm  = r >> 2;                  // batch row 0..31
    const int tn  = r & 3;                   // local unit 0..3
    const int j0  = blockIdx.x * 4;
    const int j   = j0 + tn;
    const unsigned nb = gridDim.x;

    // Load Wh slice, layout Whs[k*16 + u*4 + q] = Wh[k][q*HH + j0 + u]
    for (int idx = tid; idx < HH * 16; idx += 256) {
        int k = idx >> 4, c = idx & 15, u = c >> 2, q = c & 3;
        Whs[idx] = Wh[(size_t)k * G4 + q * HH + j0 + u];
    }

    float cst = 0.f;
    const float* hrow = hs + tm * HS_STRIDE + kh * KHALF;
    const float* wcol = Whs + (kh * KHALF) * 16 + tn * 4;
    float* myred = red + r * 4;

    // xg prefetch registers (kh=0 only)
    float xi = 0.f, xf = 0.f, xG = 0.f, xo = 0.f;
    if (kh == 0) {
        const float* xgp = g_xg + ((size_t)tm * SB + 0) * G4;
        xi = __ldcg(xgp + j);          xf = __ldcg(xgp + HH + j);
        xG = __ldcg(xgp + 2 * HH + j); xo = __ldcg(xgp + 3 * HH + j);
    }

    for (int t = 0; t < SB; t++) {
        // ---- stage h[t-1] into SMEM (padded stride, conflict-free) ----
        if (t == 0) {
            float4 z = make_float4(0.f, 0.f, 0.f, 0.f);
            for (int i = tid; i < BH / 4; i += 256) {
                int m = i >> 7, c = i & 127;
                *(float4*)(hs + m * HS_STRIDE + (c << 2)) = z;
            }
        } else {
            const float4* src = (const float4*)(g_h + (size_t)(t - 1) * BH);
            for (int i = tid; i < BH / 4; i += 256) {
                int m = i >> 7, c = i & 127;
                *(float4*)(hs + m * HS_STRIDE + (c << 2)) = __ldcg(src + m * 128 + c);
            }
        }
        __syncthreads();

        // ---- per-step GEMV: 4 gate dots over this thread's k-half ----
        unsigned long long a01_0, a23_0, a01_1 = 0ull, a23_1 = 0ull;
        if (kh == 0) { a01_0 = pack2(xi, xf); a23_0 = pack2(xG, xo); }
        else         { a01_0 = 0ull;          a23_0 = 0ull; }

        // preload group 0 (4 k values)
        float4 h0 = *(const float4*)(hrow);
        ulonglong2 wA0 = *(const ulonglong2*)(wcol);
        ulonglong2 wB0 = *(const ulonglong2*)(wcol + 16);
        ulonglong2 wC0 = *(const ulonglong2*)(wcol + 32);
        ulonglong2 wD0 = *(const ulonglong2*)(wcol + 48);

#pragma unroll 2
        for (int g = 0; g < KHALF / 4; g += 2) {
            // prefetch group g+1
            const float* hp1 = hrow + (g + 1) * 4;
            const float* wp1 = wcol + (g + 1) * 64;
            float4 h1 = *(const float4*)(hp1);
            ulonglong2 wA1 = *(const ulonglong2*)(wp1);
            ulonglong2 wB1 = *(const ulonglong2*)(wp1 + 16);
            ulonglong2 wC1 = *(const ulonglong2*)(wp1 + 32);
            ulonglong2 wD1 = *(const ulonglong2*)(wp1 + 48);

            // FMA group g -> accumulator set 0
            { unsigned long long d = dup2(h0.x); ffma2(a01_0, d, wA0.x); ffma2(a23_0, d, wA0.y); }
            { unsigned long long d = dup2(h0.y); ffma2(a01_0, d, wB0.x); ffma2(a23_0, d, wB0.y); }
            { unsigned long long d = dup2(h0.z); ffma2(a01_0, d, wC0.x); ffma2(a23_0, d, wC0.y); }
            { unsigned long long d = dup2(h0.w); ffma2(a01_0, d, wD0.x); ffma2(a23_0, d, wD0.y); }

            // prefetch group g+2 (over-reads one group at the end: lands in
            // the padded hs row tail / adjacent SMEM region, never consumed)
            const float* hp2 = hrow + (g + 2) * 4;
            const float* wp2 = wcol + (g + 2) * 64;
            h0  = *(const float4*)(hp2);
            wA0 = *(const ulonglong2*)(wp2);
            wB0 = *(const ulonglong2*)(wp2 + 16);
            wC0 = *(const ulonglong2*)(wp2 + 32);
            wD0 = *(const ulonglong2*)(wp2 + 48);

            // FMA group g+1 -> accumulator set 1
            { unsigned long long d = dup2(h1.x); ffma2(a01_1, d, wA1.x); ffma2(a23_1, d, wA1.y); }
            { unsigned long long d = dup2(h1.y); ffma2(a01_1, d, wB1.x); ffma2(a23_1, d, wB1.y); }
            { unsigned long long d = dup2(h1.z); ffma2(a01_1, d, wC1.x); ffma2(a23_1, d, wC1.y); }
            { unsigned long long d = dup2(h1.w); ffma2(a01_1, d, wD1.x); ffma2(a23_1, d, wD1.y); }
        }

        // combine accumulator sets -> 4 scalar gate partials
        float gi0, gf0, gg0, go0, gi1, gf1, gg1, go1;
        unpack2(a01_0, gi0, gf0); unpack2(a23_0, gg0, go0);
        unpack2(a01_1, gi1, gf1); unpack2(a23_1, gg1, go1);
        float gi = gi0 + gi1, gf = gf0 + gf1, gg = gg0 + gg1, go = go0 + go1;

        // ---- cross-k reduction + cell update ----
        if (kh == 1) *(float4*)myred = make_float4(gi, gf, gg, go);
        __syncthreads();
        if (kh == 0) {
            float4 p = *(const float4*)myred;
            gi += p.x; gf += p.y; gg += p.z; go += p.w;
            float si = sigm(gi), sf = sigm(gf), so = sigm(go);
            cst = sf * cst + si * tanhf(gg);
            float hn = so * tanhf(cst);
            __stcg(g_h + (size_t)t * BH + (size_t)tm * HH + j, hn);

            // prefetch xg for step t+1 (hidden behind the barrier)
            int tn1 = (t + 1 < SB) ? (t + 1) : (SB - 1);
            const float* xgp = g_xg + ((size_t)tm * SB + tn1) * G4;
            xi = __ldcg(xgp + j);          xf = __ldcg(xgp + HH + j);
            xG = __ldcg(xgp + 2 * HH + j); xo = __ldcg(xgp + 3 * HH + j);
        }

        // ---- grid barrier (sense-reversing, replay-safe, nanosleep spin) ----
        __threadfence();
        __syncthreads();
        if (tid == 0) {
            volatile unsigned* vgen = &g_bar_gen;
            unsigned g = *vgen;
            unsigned old = atomicAdd(&g_bar_cnt, 1u);
            if (old == nb - 1u) {
                atomicExch(&g_bar_cnt, 0u);
                __threadfence();
                atomicAdd(&g_bar_gen, 1u);
            } else {
                while (*vgen == g) { __nanosleep(32); }
            }
        }
        __syncthreads();
    }
}

// ---------------------------------------------------------------------------
// Launch
// ---------------------------------------------------------------------------
extern "C" void kernel_launch(void* const* d_in, const int* in_sizes, int n_in,
                              void* d_out, int out_size) {
    const float *x = nullptr, *Wx = nullptr, *Wh = nullptr,
                *b = nullptr, *Wo = nullptr, *bo = nullptr;
    for (int i = 0; i < n_in; i++) {
        switch (in_sizes[i]) {
            case BB * SB * DD: x  = (const float*)d_in[i]; break;
            case DD * G4:      Wx = (const float*)d_in[i]; break;
            case HH * G4:      Wh = (const float*)d_in[i]; break;
            case G4:           b  = (const float*)d_in[i]; break;
            case HH * OO:      Wo = (const float*)d_in[i]; break;
            case OO:           bo = (const float*)d_in[i]; break;
        }
    }

    float* xg;   cudaGetSymbolAddress((void**)&xg, g_xg);
    float* hall; cudaGetSymbolAddress((void**)&hall, g_h);

    // 1) xg = x @ Wx + b
    {
        dim3 grid(G4 / 64, (BB * SB) / 64);
        sgemm_f32x2<false><<<grid, 128>>>(x, Wx, b, xg, BB * SB, G4, DD);
    }

    // 2) persistent recurrence
    {
        int smem_bytes = (HH * 16 + 32 * HS_STRIDE + 128 * 4) * (int)sizeof(float);
        cudaFuncSetAttribute(lstm_rec, cudaFuncAttributeMaxDynamicSharedMemorySize,
                             smem_bytes);
        lstm_rec<<<HH / 4, 256, smem_bytes>>>(Wh);
    }

    // 3) y = h @ Wo + bo with [t][b] -> [b][t] remap
    {
        dim3 grid(OO / 64, (BB * SB) / 64);
        sgemm_f32x2<true><<<grid, 128>>>(hall, Wo, bo, (float*)d_out,
                                         BB * SB, OO, HH);
    }
}